// round 7
// baseline (speedup 1.0000x reference)
#include <cuda_runtime.h>
#include <cuda_fp16.h>
#include <math.h>
#include <stdint.h>

// ---------------- problem constants ----------------
#define BSZ   4
#define TN    512
#define BT    2048
#define EMB   256
#define NH    8
#define HD    32
#define HID   1024
#define VOC   50257
#define VOCP  50432

#define LOSS_OFF ((size_t)BT * VOC)
#define PROB_OFF (LOSS_OFF + 1)

// ---------------- device scratch ----------------
__device__ float g_x [BT * EMB];
__device__ float g_q [NH * BT * HD];
__device__ float g_k [NH * BT * HD];
__device__ float g_v [NH * BT * HD];
__device__ float g_sT[NH * BSZ * TN * TN];
__device__ float g_m [NH * BSZ * TN];
__device__ float g_rz[NH * BSZ * TN];
__device__ float g_ao[BT * EMB];
__device__ __half g_h  [BT * HID];
__device__ __half g_w2t[(size_t)VOCP * HID];
__device__ float g_z [BT];

// fast exp for |x| small (logits ~1e-2); guarded exact fallback
__device__ __forceinline__ float fexp(float x) {
    if (fabsf(x) > 0.25f) return __expf(x);
    float p = fmaf(x, 0.041666667f, 0.16666667f);
    p = fmaf(x, p, 0.5f);
    p = fmaf(x, p, 1.0f);
    p = fmaf(x, p, 1.0f);
    return p;
}

// ================= embed / qkv =================

__global__ void k_embed(const int* __restrict__ idx,
                        const float* __restrict__ tok,
                        const float* __restrict__ pos) {
    int i = blockIdx.x;
    int e = threadIdx.x;
    int id = idx[i];
    g_x[i * EMB + e] = tok[(size_t)id * EMB + e] + pos[(i % TN) * EMB + e];
}

__global__ void k_qkv(const float* __restrict__ Wq,
                      const float* __restrict__ Wk,
                      const float* __restrict__ Wv) {
    __shared__ float xr[EMB];
    int bt = blockIdx.x, n = blockIdx.y;
    for (int e = threadIdx.x; e < EMB; e += 96) xr[e] = g_x[bt * EMB + e];
    __syncthreads();
    int w = threadIdx.x >> 5;
    int h = threadIdx.x & 31;
    const float* W = (w == 0) ? Wq : (w == 1) ? Wk : Wv;
    const float* Wn = W + (size_t)n * EMB * HD;
    float acc = 0.f;
    #pragma unroll 8
    for (int e = 0; e < EMB; e++) acc += xr[e] * Wn[e * HD + h];
    float* dst = (w == 0) ? g_q : (w == 1) ? g_k : g_v;
    dst[((size_t)n * BT + bt) * HD + h] = acc;
}

// ================= scores: tiled Q@K^T =================
__global__ void __launch_bounds__(256)
k_score2() {
    int bi = blockIdx.x & 7;
    int bj = blockIdx.x >> 3;
    int b = blockIdx.y, n = blockIdx.z;
    int t0 = bi * 64, s0 = bj * 64;
    float* dst = &g_sT[(((size_t)(n * BSZ + b)) * TN + s0) * TN + t0];

    if (t0 + 63 < s0) {
        #pragma unroll
        for (int r = 0; r < 16; r++) {
            int idx = threadIdx.x + r * 256;
            dst[(size_t)(idx >> 6) * TN + (idx & 63)] = -1e30f;
        }
        return;
    }

    __shared__ float Qs[64][33];
    __shared__ float Ks[64][33];
    __shared__ float Os[64][65];
    int base = n * BT + b * TN;

    {
        int r = threadIdx.x >> 2;
        int c = (threadIdx.x & 3) * 8;
        const float* qp = &g_q[((size_t)(base + t0 + r)) * HD + c];
        const float* kp = &g_k[((size_t)(base + s0 + r)) * HD + c];
        float4 v0 = *(const float4*)qp, v1 = *(const float4*)(qp + 4);
        Qs[r][c + 0] = v0.x; Qs[r][c + 1] = v0.y; Qs[r][c + 2] = v0.z; Qs[r][c + 3] = v0.w;
        Qs[r][c + 4] = v1.x; Qs[r][c + 5] = v1.y; Qs[r][c + 6] = v1.z; Qs[r][c + 7] = v1.w;
        v0 = *(const float4*)kp; v1 = *(const float4*)(kp + 4);
        Ks[r][c + 0] = v0.x; Ks[r][c + 1] = v0.y; Ks[r][c + 2] = v0.z; Ks[r][c + 3] = v0.w;
        Ks[r][c + 4] = v1.x; Ks[r][c + 5] = v1.y; Ks[r][c + 6] = v1.z; Ks[r][c + 7] = v1.w;
    }
    __syncthreads();

    int tx = threadIdx.x & 15, ty = threadIdx.x >> 4;
    float acc[4][4];
    #pragma unroll
    for (int i = 0; i < 4; i++)
        #pragma unroll
        for (int j = 0; j < 4; j++) acc[i][j] = 0.f;

    #pragma unroll
    for (int h = 0; h < HD; h++) {
        float a[4], c[4];
        #pragma unroll
        for (int i = 0; i < 4; i++) a[i] = Qs[ty * 4 + i][h];
        #pragma unroll
        for (int j = 0; j < 4; j++) c[j] = Ks[tx * 4 + j][h];
        #pragma unroll
        for (int i = 0; i < 4; i++)
            #pragma unroll
            for (int j = 0; j < 4; j++) acc[i][j] += a[i] * c[j];
    }

    #pragma unroll
    for (int i = 0; i < 4; i++)
        #pragma unroll
        for (int j = 0; j < 4; j++) {
            int tt = ty * 4 + i, ss = tx * 4 + j;
            Os[ss][tt] = (t0 + tt >= s0 + ss) ? acc[i][j] * 0.0625f : -1e30f;
        }
    __syncthreads();
    #pragma unroll
    for (int r = 0; r < 16; r++) {
        int idx = threadIdx.x + r * 256;
        int ss = idx >> 6, tt = idx & 63;
        dst[(size_t)ss * TN + tt] = Os[ss][tt];
    }
}

// ================= column stats =================
__global__ void k_stats() {
    int s = blockIdx.x, b = blockIdx.y, n = blockIdx.z;
    const float* row = &g_sT[(((size_t)n * BSZ + b) * TN + s) * TN];
    __shared__ float red[256];
    float m = -1e30f;
    for (int t = threadIdx.x; t < TN; t += 256) m = fmaxf(m, row[t]);
    red[threadIdx.x] = m; __syncthreads();
    for (int o = 128; o > 0; o >>= 1) {
        if (threadIdx.x < o) red[threadIdx.x] = fmaxf(red[threadIdx.x], red[threadIdx.x + o]);
        __syncthreads();
    }
    m = red[0]; __syncthreads();
    float z = 0.f;
    for (int t = threadIdx.x; t < TN; t += 256) z += __expf(row[t] - m);
    red[threadIdx.x] = z; __syncthreads();
    for (int o = 128; o > 0; o >>= 1) {
        if (threadIdx.x < o) red[threadIdx.x] += red[threadIdx.x + o];
        __syncthreads();
    }
    if (threadIdx.x == 0) {
        size_t off = ((size_t)n * BSZ + b) * TN + s;
        g_m[off] = m;
        g_rz[off] = 1.0f / red[0];
    }
}

// ================= attention out: tiled W@V =================
__global__ void __launch_bounds__(256)
k_attnout2() {
    int bt = blockIdx.x;
    int b = blockIdx.y, n = blockIdx.z;
    int t0 = bt * 64;
    size_t nb = (size_t)n * BSZ + b;
    const float* sT = &g_sT[nb * TN * TN];
    const float* v  = &g_v[((size_t)n * BT + b * TN) * HD];

    __shared__ float Ws[64][65];
    __shared__ float Vs[64][33];
    __shared__ float mr[64], zr[64];

    int tx = threadIdx.x & 15, ty = threadIdx.x >> 4;
    float acc[4][2];
    #pragma unroll
    for (int i = 0; i < 4; i++) { acc[i][0] = 0.f; acc[i][1] = 0.f; }

    for (int sb = 0; sb <= bt; sb++) {
        int s0 = sb * 64;
        if (threadIdx.x < 64) {
            mr[threadIdx.x] = g_m [nb * TN + s0 + threadIdx.x];
            zr[threadIdx.x] = g_rz[nb * TN + s0 + threadIdx.x];
        }
        __syncthreads();
        #pragma unroll
        for (int r = 0; r < 16; r++) {
            int idx = threadIdx.x + r * 256;
            int ss = idx >> 6, tt = idx & 63;
            float sv = sT[(size_t)(s0 + ss) * TN + t0 + tt];
            Ws[ss][tt] = __expf(sv - mr[ss]) * zr[ss];
        }
        {
            int r = threadIdx.x >> 2;
            int c = (threadIdx.x & 3) * 8;
            const float* vp = &v[(size_t)(s0 + r) * HD + c];
            float4 v0 = *(const float4*)vp, v1 = *(const float4*)(vp + 4);
            Vs[r][c + 0] = v0.x; Vs[r][c + 1] = v0.y; Vs[r][c + 2] = v0.z; Vs[r][c + 3] = v0.w;
            Vs[r][c + 4] = v1.x; Vs[r][c + 5] = v1.y; Vs[r][c + 6] = v1.z; Vs[r][c + 7] = v1.w;
        }
        __syncthreads();
        #pragma unroll 8
        for (int ss = 0; ss < 64; ss++) {
            float w0 = Ws[ss][ty * 4 + 0];
            float w1 = Ws[ss][ty * 4 + 1];
            float w2 = Ws[ss][ty * 4 + 2];
            float w3 = Ws[ss][ty * 4 + 3];
            float va = Vs[ss][tx * 2 + 0];
            float vb = Vs[ss][tx * 2 + 1];
            acc[0][0] += w0 * va; acc[0][1] += w0 * vb;
            acc[1][0] += w1 * va; acc[1][1] += w1 * vb;
            acc[2][0] += w2 * va; acc[2][1] += w2 * vb;
            acc[3][0] += w3 * va; acc[3][1] += w3 * vb;
        }
        __syncthreads();
    }

    #pragma unroll
    for (int i = 0; i < 4; i++) {
        int t = t0 + ty * 4 + i;
        int h = tx * 2;
        float* op = &g_ao[((size_t)(b * TN + t)) * EMB + n * HD + h];
        op[0] = acc[i][0];
        op[1] = acc[i][1];
    }
}

// ================= FF1 (fp16 output) =================
__global__ void k_ff1(const float* __restrict__ W1, const float* __restrict__ b1) {
    __shared__ float xr[EMB];
    int bt = blockIdx.x;
    xr[threadIdx.x] = g_ao[(size_t)bt * EMB + threadIdx.x];
    __syncthreads();
    float acc[4] = {0.f, 0.f, 0.f, 0.f};
    for (int e = 0; e < EMB; e++) {
        float xv = xr[e];
        const float* wr = &W1[(size_t)e * HID];
        #pragma unroll
        for (int j = 0; j < 4; j++) acc[j] += xv * wr[threadIdx.x + j * 256];
    }
    #pragma unroll
    for (int j = 0; j < 4; j++) {
        int c = threadIdx.x + j * 256;
        g_h[(size_t)bt * HID + c] = __float2half_rn(fmaxf(acc[j] + b1[c], 0.f));
    }
}

// transpose W2 [HID, VOC] -> g_w2t [VOCP, HID] (fp16, zero-padded)
__global__ void k_transpose(const float* __restrict__ W2) {
    __shared__ float t[32][33];
    int nb = blockIdx.x * 32, kb = blockIdx.y * 32;
    int tx = threadIdx.x, ty = threadIdx.y;
    #pragma unroll
    for (int i = 0; i < 32; i += 8) {
        int k = kb + ty + i, n = nb + tx;
        t[ty + i][tx] = (n < VOC) ? W2[(size_t)k * VOC + n] : 0.f;
    }
    __syncthreads();
    #pragma unroll
    for (int i = 0; i < 32; i += 8) {
        int n = nb + ty + i, k = kb + tx;
        g_w2t[(size_t)n * HID + k] = __float2half_rn(t[tx][ty + i]);
    }
}

// ================= fp16 m16n8k16 LM-head GEMM (ldmatrix) ===============
#define MT    128
#define NTL   128
#define KCH   64                            // halves per K chunk
#define SAH   72                            // padded row stride in halves (144 B)
#define STAGE_H (MT * SAH)
#define STAGE_B2 (STAGE_H * 2)              // 18432 bytes
#define GSMEM (4 * STAGE_B2)

__device__ __forceinline__ uint32_t s2u(const void* p) {
    uint32_t a;
    asm("{ .reg .u64 t; cvta.to.shared.u64 t, %1; cvt.u32.u64 %0, t; }" : "=r"(a) : "l"(p));
    return a;
}
__device__ __forceinline__ void ldgsts16(uint32_t s, const void* g) {
    asm volatile("cp.async.cg.shared.global [%0], [%1], 16;" :: "r"(s), "l"(g));
}
#define CP_COMMIT() asm volatile("cp.async.commit_group;" ::: "memory")
#define CP_WAIT(n)  asm volatile("cp.async.wait_group %0;" :: "n"(n) : "memory")

#define LDSM4(r0, r1, r2, r3, addr) \
    asm volatile("ldmatrix.sync.aligned.m8n8.x4.shared.b16 {%0,%1,%2,%3}, [%4];" \
                 : "=r"(r0), "=r"(r1), "=r"(r2), "=r"(r3) : "r"(addr))

__device__ __forceinline__ void mma_fp16(float* d, const uint32_t* a, const uint32_t* b) {
    asm volatile(
        "mma.sync.aligned.m16n8k16.row.col.f32.f16.f16.f32 "
        "{%0,%1,%2,%3}, {%4,%5,%6,%7}, {%8,%9}, {%0,%1,%2,%3};"
        : "+f"(d[0]), "+f"(d[1]), "+f"(d[2]), "+f"(d[3])
        : "r"(a[0]), "r"(a[1]), "r"(a[2]), "r"(a[3]), "r"(b[0]), "r"(b[1]));
}

__global__ void __launch_bounds__(256, 2)
k_gemm_tc(const float* __restrict__ b2, float* __restrict__ out) {
    extern __shared__ __half smh[];
    uint32_t smb = s2u(smh);
    int tid = threadIdx.x;
    int wid = tid >> 5, lane = tid & 31;
    int wm = wid & 3, wn = wid >> 2;
    int lq = lane >> 2, lr = lane & 3;
    int bm = blockIdx.x * MT;
    int bn = blockIdx.y * NTL;

    const __half* Ag = &g_h  [(size_t)bm * HID];
    const __half* Bg = &g_w2t[(size_t)bn * HID];

    // ldmatrix lane mapping: tiles of 8 lanes; within-tile row + k-half
    uint32_t lrow = (lane & 7) + ((lane >> 3) & 1) * 8;   // 0..15
    uint32_t lkh  = (lane >> 4) * 8;                      // 0 or 8 halves

    float acc[2][8][4];
    #pragma unroll
    for (int i = 0; i < 2; i++)
        #pragma unroll
        for (int j = 0; j < 8; j++)
            #pragma unroll
            for (int q = 0; q < 4; q++) acc[i][j][q] = 0.f;

    auto load_chunk = [&](int st, int c) {
        uint32_t abase = smb + st * 2u * STAGE_B2;
        uint32_t bbase = abase + STAGE_B2;
        #pragma unroll
        for (int i = 0; i < 4; i++) {
            int j = tid + i * 256;
            int row = j >> 3, f8 = j & 7;
            uint32_t so = (uint32_t)(row * SAH + f8 * 8) * 2u;
            size_t go = (size_t)row * HID + c * KCH + f8 * 8;
            ldgsts16(abase + so, Ag + go);
            ldgsts16(bbase + so, Bg + go);
        }
        CP_COMMIT();
    };

    load_chunk(0, 0);

    const int NCH = HID / KCH;
    for (int c = 0; c < NCH; c++) {
        int st = c & 1;
        if (c + 1 < NCH) { load_chunk(st ^ 1, c + 1); CP_WAIT(1); }
        else             { CP_WAIT(0); }
        __syncthreads();

        uint32_t sbase = smb + st * 2u * STAGE_B2;
        uint32_t aaddr = sbase + ((wm * 32 + lrow) * SAH + lkh) * 2u;
        uint32_t baddr = sbase + STAGE_B2 + ((wn * 64 + lrow) * SAH + lkh) * 2u;

        #pragma unroll
        for (int k0 = 0; k0 < KCH; k0 += 16) {
            uint32_t a[2][4], b[8][2];
            #pragma unroll
            for (int mt = 0; mt < 2; mt++)
                LDSM4(a[mt][0], a[mt][1], a[mt][2], a[mt][3],
                      aaddr + (uint32_t)(mt * 16 * SAH + k0) * 2u);
            #pragma unroll
            for (int j = 0; j < 4; j++)
                LDSM4(b[2 * j][0], b[2 * j + 1][0], b[2 * j][1], b[2 * j + 1][1],
                      baddr + (uint32_t)(j * 16 * SAH + k0) * 2u);
            #pragma unroll
            for (int mt = 0; mt < 2; mt++)
                #pragma unroll
                for (int nt = 0; nt < 8; nt++)
                    mma_fp16(acc[mt][nt], a[mt], b[nt]);
        }
        __syncthreads();
    }

    // epilogue: store logits, accumulate z with poly exp
    float zp[4] = {0.f, 0.f, 0.f, 0.f};
    #pragma unroll
    for (int mt = 0; mt < 2; mt++) {
        int m0 = bm + wm * 32 + mt * 16 + lq;
        #pragma unroll
        for (int nt = 0; nt < 8; nt++) {
            int n = bn + wn * 64 + nt * 8 + lr * 2;
            if (n >= VOC) continue;
            float bb0 = b2[n];
            size_t o0 = (size_t)m0 * VOC + n;
            size_t o1 = (size_t)(m0 + 8) * VOC + n;
            float v00 = acc[mt][nt][0] + bb0;
            float v10 = acc[mt][nt][2] + bb0;
            out[o0] = v00; out[o1] = v10;
            zp[mt * 2 + 0] += fexp(v00); zp[mt * 2 + 1] += fexp(v10);
            if (n + 1 < VOC) {
                float bb1 = b2[n + 1];
                float v01 = acc[mt][nt][1] + bb1;
                float v11 = acc[mt][nt][3] + bb1;
                out[o0 + 1] = v01; out[o1 + 1] = v11;
                zp[mt * 2 + 0] += fexp(v01); zp[mt * 2 + 1] += fexp(v11);
            }
        }
    }
    #pragma unroll
    for (int mt = 0; mt < 2; mt++) {
        int m0 = bm + wm * 32 + mt * 16 + lq;
        atomicAdd(&g_z[m0],     zp[mt * 2 + 0]);
        atomicAdd(&g_z[m0 + 8], zp[mt * 2 + 1]);
    }
}

// ================= finalize: o_prob from logits + loss =================
__global__ void k_zero_z(float* out) {
    int i = blockIdx.x * 1024 + threadIdx.x;
    if (i < BT) g_z[i] = 0.f;
    if (i == 0) out[LOSS_OFF] = 0.f;
}

__global__ void k_finalize(const int* __restrict__ targets, float* __restrict__ out) {
    int r = blockIdx.x;
    float z = g_z[r];
    float rz = 1.0f / z;
    const float* lg = out + (size_t)r * VOC;
    float* op = out + PROB_OFF + (size_t)r * VOC;
    for (int c = threadIdx.x; c < VOC; c += 1024) op[c] = fexp(lg[c]) * rz;
    if (threadIdx.x == 0) {
        float logp = lg[targets[r]] - logf(z);
        atomicAdd(out + LOSS_OFF, -logp * (1.0f / BT));
    }
}

// ================= host launch =================
extern "C" void kernel_launch(void* const* d_in, const int* in_sizes, int n_in,
                              void* d_out, int out_size) {
    const int*   idx     = (const int*)  d_in[0];
    const int*   targets = (const int*)  d_in[1];
    const float* tok_emb = (const float*)d_in[2];
    const float* pos_emb = (const float*)d_in[3];
    const float* Wq      = (const float*)d_in[4];
    const float* Wk      = (const float*)d_in[5];
    const float* Wv      = (const float*)d_in[6];
    const float* W1      = (const float*)d_in[7];
    const float* b1      = (const float*)d_in[8];
    const float* W2      = (const float*)d_in[9];
    const float* b2      = (const float*)d_in[10];
    float* out = (float*)d_out;

    cudaFuncSetAttribute(k_gemm_tc, cudaFuncAttributeMaxDynamicSharedMemorySize, GSMEM);

    {
        dim3 g(VOCP / 32, HID / 32), b(32, 8);
        k_transpose<<<g, b>>>(W2);
    }
    k_embed<<<BT, EMB>>>(idx, tok_emb, pos_emb);
    {
        dim3 g(BT, NH);
        k_qkv<<<g, 96>>>(Wq, Wk, Wv);
    }
    {
        dim3 g(64, BSZ, NH);
        k_score2<<<g, 256>>>();
    }
    {
        dim3 g(TN, BSZ, NH);
        k_stats<<<g, 256>>>();
    }
    {
        dim3 g(TN / 64, BSZ, NH);
        k_attnout2<<<g, 256>>>();
    }
    k_ff1<<<BT, 256>>>(W1, b1);
    k_zero_z<<<2, 1024>>>(out);
    {
        dim3 g(BT / MT, VOCP / NTL);
        k_gemm_tc<<<g, 256, GSMEM>>>(b2, out);
    }
    k_finalize<<<BT, 1024>>>(targets, out);
}